// round 1
// baseline (speedup 1.0000x reference)
#include <cuda_runtime.h>
#include <cuda_bf16.h>

// ---------------------------------------------------------------------------
// BasicAttention: B=8, C=1024, L=2048, A=128
//   keys    = Wk @ x + bk              [B,128,2048]
//   queries = Wq @ x + bq              [B,128,2048]
//   values  = keys^T @ queries         [B,2048,2048]
//   attn    = softmax(values / 1024)   (seqlen/2 scale)
//   out1    = x @ attn                 [B,1024,2048]
//   out     = Wp @ out1 + bp           [B,1024,2048]
// ---------------------------------------------------------------------------

#define BATCH 8
#define CDIM 1024
#define LDIM 2048
#define ADIM 128

// Scratch (static __device__ globals; allocation inside kernel_launch is forbidden)
__device__ float g_w2[256 * 1024];                       // stacked [Wk; Wq]
__device__ float g_b2[256];                              // stacked [bk; bq]
__device__ float g_kq[BATCH * 256 * LDIM];               // stacked keys(0:128)/queries(128:256)
__device__ float g_vals[(long long)BATCH * LDIM * LDIM]; // logits / attn (in-place softmax)
__device__ float g_out1[BATCH * CDIM * LDIM];            // x @ attn

#define BM 128
#define BN 128
#define BK 8

// Generic batched SGEMM:
//   ATRANS=false: C[m,n] = sum_k A[m*lda + k] * B[k*ldb + n]   (A row-major [M,K])
//   ATRANS=true : C[m,n] = sum_k A[k*lda + m] * B[k*ldb + n]   (A stored [K,M])
// Optional bias[m] added per output row. All of M,N divisible by 128, K by 8.
template <bool ATRANS, bool BIAS>
__global__ void __launch_bounds__(256) sgemm_kernel(
    const float* __restrict__ A, const float* __restrict__ B,
    const float* __restrict__ bias, float* __restrict__ C,
    int M, int N, int K, int lda, int ldb, int ldc,
    long long strideA, long long strideB, long long strideC)
{
    __shared__ float As[BK][BM];
    __shared__ float Bs[BK][BN];

    const int bz = blockIdx.z;
    A += (long long)bz * strideA;
    B += (long long)bz * strideB;
    C += (long long)bz * strideC;

    const int tid = threadIdx.x;
    const int tx = tid & 15;        // 0..15 -> output cols tx*8..tx*8+7
    const int ty = tid >> 4;        // 0..15 -> output rows ty*8..ty*8+7
    const int row0 = blockIdx.y * BM;
    const int col0 = blockIdx.x * BN;

    // B-tile (and ATRANS A-tile) loader indices: 8 k-rows x 32 float4
    const int lk  = tid >> 5;           // 0..7
    const int ln4 = (tid & 31) << 2;    // 0,4,...,124
    // NN A-tile loader indices: 128 rows x 2 float4 along K
    const int ar  = tid >> 1;           // 0..127
    const int ak4 = (tid & 1) << 2;     // 0 or 4

    float acc[8][8];
#pragma unroll
    for (int i = 0; i < 8; ++i)
#pragma unroll
        for (int j = 0; j < 8; ++j) acc[i][j] = 0.0f;

    for (int k0 = 0; k0 < K; k0 += BK) {
        // ---- load B tile [BK x BN]
        float4 bv = *(const float4*)(B + (long long)(k0 + lk) * ldb + col0 + ln4);
        *(float4*)(&Bs[lk][ln4]) = bv;

        // ---- load A tile into As[k][m]
        if (ATRANS) {
            float4 av = *(const float4*)(A + (long long)(k0 + lk) * lda + row0 + ln4);
            *(float4*)(&As[lk][ln4]) = av;
        } else {
            float4 av = *(const float4*)(A + (long long)(row0 + ar) * lda + k0 + ak4);
            As[ak4 + 0][ar] = av.x;
            As[ak4 + 1][ar] = av.y;
            As[ak4 + 2][ar] = av.z;
            As[ak4 + 3][ar] = av.w;
        }
        __syncthreads();

#pragma unroll
        for (int kk = 0; kk < BK; ++kk) {
            float ra[8], rb[8];
            *(float4*)(ra)     = *(const float4*)(&As[kk][ty * 8]);
            *(float4*)(ra + 4) = *(const float4*)(&As[kk][ty * 8 + 4]);
            *(float4*)(rb)     = *(const float4*)(&Bs[kk][tx * 8]);
            *(float4*)(rb + 4) = *(const float4*)(&Bs[kk][tx * 8 + 4]);
#pragma unroll
            for (int i = 0; i < 8; ++i)
#pragma unroll
                for (int j = 0; j < 8; ++j)
                    acc[i][j] = fmaf(ra[i], rb[j], acc[i][j]);
        }
        __syncthreads();
    }

#pragma unroll
    for (int i = 0; i < 8; ++i) {
        const int row = row0 + ty * 8 + i;
        const float bval = BIAS ? bias[row] : 0.0f;
        float* cptr = C + (long long)row * ldc + col0 + tx * 8;
        float4 o0, o1;
        o0.x = acc[i][0] + bval; o0.y = acc[i][1] + bval;
        o0.z = acc[i][2] + bval; o0.w = acc[i][3] + bval;
        o1.x = acc[i][4] + bval; o1.y = acc[i][5] + bval;
        o1.z = acc[i][6] + bval; o1.w = acc[i][7] + bval;
        *(float4*)(cptr)     = o0;
        *(float4*)(cptr + 4) = o1;
    }
}

// Concatenate [Wk;Wq] -> g_w2, [bk;bq] -> g_b2
__global__ void concat_w_kernel(const float* __restrict__ Wk, const float* __restrict__ bk,
                                const float* __restrict__ Wq, const float* __restrict__ bq)
{
    int i = blockIdx.x * blockDim.x + threadIdx.x;
    const int half = 128 * 1024;
    if (i < half)            g_w2[i] = Wk[i];
    else if (i < 2 * half)   g_w2[i] = Wq[i - half];
    if (i < 128)             g_b2[i] = bk[i];
    else if (i < 256)        g_b2[i] = bq[i - 128];
}

__device__ __forceinline__ float warp_max(float v) {
#pragma unroll
    for (int o = 16; o > 0; o >>= 1) v = fmaxf(v, __shfl_xor_sync(0xffffffffu, v, o));
    return v;
}
__device__ __forceinline__ float warp_sum(float v) {
#pragma unroll
    for (int o = 16; o > 0; o >>= 1) v += __shfl_xor_sync(0xffffffffu, v, o);
    return v;
}

// In-place row softmax of logits/1024 over rows of length 2048.
__global__ void __launch_bounds__(256) softmax_kernel(float* __restrict__ V)
{
    float* p = V + (long long)blockIdx.x * LDIM;
    const int tid = threadIdx.x;

    float4 a = ((const float4*)p)[tid * 2];
    float4 b = ((const float4*)p)[tid * 2 + 1];
    const float s = 1.0f / 1024.0f;
    float v[8] = { a.x * s, a.y * s, a.z * s, a.w * s,
                   b.x * s, b.y * s, b.z * s, b.w * s };

    float m = v[0];
#pragma unroll
    for (int i = 1; i < 8; ++i) m = fmaxf(m, v[i]);
    m = warp_max(m);

    __shared__ float red[8];
    if ((tid & 31) == 0) red[tid >> 5] = m;
    __syncthreads();
    m = red[0];
#pragma unroll
    for (int i = 1; i < 8; ++i) m = fmaxf(m, red[i]);
    __syncthreads();

    float sum = 0.0f;
#pragma unroll
    for (int i = 0; i < 8; ++i) { v[i] = __expf(v[i] - m); sum += v[i]; }
    sum = warp_sum(sum);
    if ((tid & 31) == 0) red[tid >> 5] = sum;
    __syncthreads();
    sum = red[0];
#pragma unroll
    for (int i = 1; i < 8; ++i) sum += red[i];

    const float inv = 1.0f / sum;
    a.x = v[0] * inv; a.y = v[1] * inv; a.z = v[2] * inv; a.w = v[3] * inv;
    b.x = v[4] * inv; b.y = v[5] * inv; b.z = v[6] * inv; b.w = v[7] * inv;
    ((float4*)p)[tid * 2]     = a;
    ((float4*)p)[tid * 2 + 1] = b;
}

extern "C" void kernel_launch(void* const* d_in, const int* in_sizes, int n_in,
                              void* d_out, int out_size)
{
    const float* x  = (const float*)d_in[0];
    const float* Wk = (const float*)d_in[1];
    const float* bk = (const float*)d_in[2];
    const float* Wq = (const float*)d_in[3];
    const float* bq = (const float*)d_in[4];
    const float* Wp = (const float*)d_in[5];
    const float* bp = (const float*)d_in[6];
    float* out = (float*)d_out;

    float *p_w2, *p_b2, *p_kq, *p_vals, *p_out1;
    cudaGetSymbolAddress((void**)&p_w2,   g_w2);
    cudaGetSymbolAddress((void**)&p_b2,   g_b2);
    cudaGetSymbolAddress((void**)&p_kq,   g_kq);
    cudaGetSymbolAddress((void**)&p_vals, g_vals);
    cudaGetSymbolAddress((void**)&p_out1, g_out1);

    // 0) stack Wk/Wq and bk/bq
    concat_w_kernel<<<(256 * 1024 + 255) / 256, 256>>>(Wk, bk, Wq, bq);

    // 1) keys+queries: [256,2048] = W2[256,1024] @ x[b][1024,2048] + b2
    sgemm_kernel<false, true><<<dim3(LDIM / BN, 256 / BM, BATCH), 256>>>(
        p_w2, x, p_b2, p_kq,
        256, LDIM, CDIM, CDIM, LDIM, LDIM,
        0LL, (long long)CDIM * LDIM, (long long)256 * LDIM);

    // 2) logits: vals[l,m] = sum_a keys[a,l] * queries[a,m]   (K=128)
    sgemm_kernel<true, false><<<dim3(LDIM / BN, LDIM / BM, BATCH), 256>>>(
        p_kq, p_kq + 128 * LDIM, nullptr, p_vals,
        LDIM, LDIM, ADIM, LDIM, LDIM, LDIM,
        (long long)256 * LDIM, (long long)256 * LDIM, (long long)LDIM * LDIM);

    // 3) softmax rows (in place), scale 1/1024
    softmax_kernel<<<BATCH * LDIM, 256>>>(p_vals);

    // 4) out1[c,m] = sum_l x[c,l] * attn[l,m]   (K=2048, dominant GEMM)
    sgemm_kernel<false, false><<<dim3(LDIM / BN, CDIM / BM, BATCH), 256>>>(
        x, p_vals, nullptr, p_out1,
        CDIM, LDIM, LDIM, LDIM, LDIM, LDIM,
        (long long)CDIM * LDIM, (long long)LDIM * LDIM, (long long)CDIM * LDIM);

    // 5) out[d,m] = sum_c Wp[d,c] * out1[c,m] + bp[d]
    sgemm_kernel<false, true><<<dim3(LDIM / BN, CDIM / BM, BATCH), 256>>>(
        Wp, p_out1, bp, out,
        CDIM, LDIM, CDIM, CDIM, LDIM, LDIM,
        0LL, (long long)CDIM * LDIM, (long long)CDIM * LDIM);
}

// round 2
// speedup vs baseline: 3.1729x; 3.1729x over previous
#include <cuda_runtime.h>
#include <cuda_bf16.h>
#include <cstdint>

// ---------------------------------------------------------------------------
// BasicAttention: B=8, C=1024, L=2048, A=128
//   keys/queries = [Wk;Wq] @ x + [bk;bq]       (fused, M=256)
//   values  = keys^T @ queries                  [B,2048,2048]
//   attn    = softmax(values / 1024)
//   out1    = x @ attn
//   out     = Wp @ out1 + bp
// All GEMMs: TF32 mma.sync.m16n8k8, cp.async double-buffered 128x128x16 tiles.
// ---------------------------------------------------------------------------

#define BATCH 8
#define CDIM 1024
#define LDIM 2048
#define ADIM 128

__device__ float g_w2[256 * 1024];
__device__ float g_b2[256];
__device__ float g_kq[BATCH * 256 * LDIM];
__device__ float g_kT[BATCH * LDIM * ADIM];
__device__ float g_vals[(long long)BATCH * LDIM * LDIM];
__device__ float g_out1[BATCH * CDIM * LDIM];

#define BM 128
#define BN 128
#define BK 16
#define AS_STRIDE 20    // (row*20 + col) banks conflict-free for frag loads
#define BS_STRIDE 136   // (k*136 + n)   banks conflict-free for frag loads

__device__ __forceinline__ uint32_t f2tf(float f) {
    uint32_t u;
    asm("cvt.rna.tf32.f32 %0, %1;" : "=r"(u) : "f"(f));
    return u;
}

__device__ __forceinline__ void mma_tf32(float* c, const uint32_t* a, const uint32_t* b) {
    asm volatile(
        "mma.sync.aligned.m16n8k8.row.col.f32.tf32.tf32.f32 "
        "{%0,%1,%2,%3}, {%4,%5,%6,%7}, {%8,%9}, {%0,%1,%2,%3};"
        : "+f"(c[0]), "+f"(c[1]), "+f"(c[2]), "+f"(c[3])
        : "r"(a[0]), "r"(a[1]), "r"(a[2]), "r"(a[3]), "r"(b[0]), "r"(b[1]));
}

#define CP_ASYNC16(dst, src) \
    asm volatile("cp.async.cg.shared.global [%0], [%1], 16;" :: "r"(dst), "l"(src))
#define CP_COMMIT() asm volatile("cp.async.commit_group;")
#define CP_WAIT0()  asm volatile("cp.async.wait_group 0;")

// NN TF32 GEMM: C[m,n] = sum_k A[m*lda+k] * B[k*ldb+n] (+ bias[m])
// Requires M%128==0 (per grid), N%128==0, K%16==0, lda/ldb multiples of 4.
template <bool BIAS>
__global__ void __launch_bounds__(256, 2) tf32_gemm_kernel(
    const float* __restrict__ A, const float* __restrict__ B,
    const float* __restrict__ bias, float* __restrict__ C,
    int K, int lda, int ldb, int ldc,
    long long strideA, long long strideB, long long strideC)
{
    __shared__ float As[2][BM][AS_STRIDE];
    __shared__ float Bs[2][BK][BS_STRIDE];

    const int bz = blockIdx.z;
    A += (long long)bz * strideA;
    B += (long long)bz * strideB;
    C += (long long)bz * strideC;

    const int tid  = threadIdx.x;
    const int lane = tid & 31;
    const int wid  = tid >> 5;
    const int warp_m = wid >> 2;      // 0..1 -> 64-row slabs
    const int warp_n = wid & 3;       // 0..3 -> 32-col slabs
    const int g = lane >> 2;          // 0..7
    const int t = lane & 3;           // 0..3

    const int row0 = blockIdx.y * BM;
    const int col0 = blockIdx.x * BN;

    // global->shared load indices
    const int a_row = tid >> 2;            // 0..63 (and +64)
    const int a_kc  = (tid & 3) << 2;      // 0,4,8,12
    const int b_k   = tid >> 5;            // 0..7 (and +8)
    const int b_n4  = (tid & 31) << 2;     // 0..124

    float acc[4][4][4];
#pragma unroll
    for (int mt = 0; mt < 4; ++mt)
#pragma unroll
        for (int nt = 0; nt < 4; ++nt)
#pragma unroll
            for (int i = 0; i < 4; ++i) acc[mt][nt][i] = 0.0f;

    const int ntiles = K / BK;

    auto issue_loads = [&](int k0, int buf) {
        // A tile: 128 rows x 16 cols, 2 float4 per thread
#pragma unroll
        for (int r = 0; r < 2; ++r) {
            int row = a_row + r * 64;
            const float* src = A + (long long)(row0 + row) * lda + k0 + a_kc;
            uint32_t dst = (uint32_t)__cvta_generic_to_shared(&As[buf][row][a_kc]);
            CP_ASYNC16(dst, src);
        }
        // B tile: 16 rows x 128 cols, 2 float4 per thread
#pragma unroll
        for (int r = 0; r < 2; ++r) {
            int kr = b_k + r * 8;
            const float* src = B + (long long)(k0 + kr) * ldb + col0 + b_n4;
            uint32_t dst = (uint32_t)__cvta_generic_to_shared(&Bs[buf][kr][b_n4]);
            CP_ASYNC16(dst, src);
        }
        CP_COMMIT();
    };

    issue_loads(0, 0);
    int buf = 0;

    for (int kt = 0; kt < ntiles; ++kt) {
        CP_WAIT0();
        __syncthreads();
        if (kt + 1 < ntiles) issue_loads((kt + 1) * BK, buf ^ 1);

#pragma unroll
        for (int kk = 0; kk < BK; kk += 8) {
            uint32_t afr[4][4];
#pragma unroll
            for (int mt = 0; mt < 4; ++mt) {
                int row = warp_m * 64 + mt * 16 + g;
                afr[mt][0] = f2tf(As[buf][row][kk + t]);
                afr[mt][1] = f2tf(As[buf][row + 8][kk + t]);
                afr[mt][2] = f2tf(As[buf][row][kk + t + 4]);
                afr[mt][3] = f2tf(As[buf][row + 8][kk + t + 4]);
            }
            uint32_t bfr[4][2];
#pragma unroll
            for (int nt = 0; nt < 4; ++nt) {
                int cn = warp_n * 32 + nt * 8 + g;
                bfr[nt][0] = f2tf(Bs[buf][kk + t][cn]);
                bfr[nt][1] = f2tf(Bs[buf][kk + t + 4][cn]);
            }
#pragma unroll
            for (int mt = 0; mt < 4; ++mt)
#pragma unroll
                for (int nt = 0; nt < 4; ++nt)
                    mma_tf32(acc[mt][nt], afr[mt], bfr[nt]);
        }
        __syncthreads();
        buf ^= 1;
    }

    // Epilogue: c0 (g, 2t), c1 (g, 2t+1), c2 (g+8, 2t), c3 (g+8, 2t+1)
#pragma unroll
    for (int mt = 0; mt < 4; ++mt) {
        int rowA = row0 + warp_m * 64 + mt * 16 + g;
        float bv0 = BIAS ? bias[rowA] : 0.0f;
        float bv1 = BIAS ? bias[rowA + 8] : 0.0f;
#pragma unroll
        for (int nt = 0; nt < 4; ++nt) {
            int col = col0 + warp_n * 32 + nt * 8 + 2 * t;
            float2 v0 = { acc[mt][nt][0] + bv0, acc[mt][nt][1] + bv0 };
            float2 v1 = { acc[mt][nt][2] + bv1, acc[mt][nt][3] + bv1 };
            *(float2*)(C + (long long)rowA * ldc + col) = v0;
            *(float2*)(C + (long long)(rowA + 8) * ldc + col) = v1;
        }
    }
}

// Concatenate [Wk;Wq] -> g_w2, [bk;bq] -> g_b2
__global__ void concat_w_kernel(const float* __restrict__ Wk, const float* __restrict__ bk,
                                const float* __restrict__ Wq, const float* __restrict__ bq)
{
    int i = blockIdx.x * blockDim.x + threadIdx.x;
    const int half = 128 * 1024;
    if (i < half)            g_w2[i] = Wk[i];
    else if (i < 2 * half)   g_w2[i] = Wq[i - half];
    if (i < 128)             g_b2[i] = bk[i];
    else if (i < 256)        g_b2[i] = bq[i - 128];
}

// keys [B,128,2048] -> keysT [B,2048,128]
__global__ void transpose_kernel(const float* __restrict__ in, float* __restrict__ outp)
{
    __shared__ float tile[32][33];
    const int bz = blockIdx.z;
    in   += (long long)bz * 256 * LDIM;     // keys live in first 128 rows of kq
    outp += (long long)bz * LDIM * ADIM;

    int x = blockIdx.x * 32 + threadIdx.x;  // l index
    int y = blockIdx.y * 32 + threadIdx.y;  // a index
#pragma unroll
    for (int j = 0; j < 32; j += 8)
        tile[threadIdx.y + j][threadIdx.x] = in[(long long)(y + j) * LDIM + x];
    __syncthreads();
    int x2 = blockIdx.y * 32 + threadIdx.x; // a index
    int y2 = blockIdx.x * 32 + threadIdx.y; // l index
#pragma unroll
    for (int j = 0; j < 32; j += 8)
        outp[(long long)(y2 + j) * ADIM + x2] = tile[threadIdx.x][threadIdx.y + j];
}

__device__ __forceinline__ float warp_max(float v) {
#pragma unroll
    for (int o = 16; o > 0; o >>= 1) v = fmaxf(v, __shfl_xor_sync(0xffffffffu, v, o));
    return v;
}
__device__ __forceinline__ float warp_sum(float v) {
#pragma unroll
    for (int o = 16; o > 0; o >>= 1) v += __shfl_xor_sync(0xffffffffu, v, o);
    return v;
}

// In-place row softmax of logits/1024 over rows of length 2048.
__global__ void __launch_bounds__(256) softmax_kernel(float* __restrict__ V)
{
    float* p = V + (long long)blockIdx.x * LDIM;
    const int tid = threadIdx.x;

    float4 a = ((const float4*)p)[tid * 2];
    float4 b = ((const float4*)p)[tid * 2 + 1];
    const float s = 1.0f / 1024.0f;
    float v[8] = { a.x * s, a.y * s, a.z * s, a.w * s,
                   b.x * s, b.y * s, b.z * s, b.w * s };

    float m = v[0];
#pragma unroll
    for (int i = 1; i < 8; ++i) m = fmaxf(m, v[i]);
    m = warp_max(m);

    __shared__ float red[8];
    if ((tid & 31) == 0) red[tid >> 5] = m;
    __syncthreads();
    m = red[0];
#pragma unroll
    for (int i = 1; i < 8; ++i) m = fmaxf(m, red[i]);
    __syncthreads();

    float sum = 0.0f;
#pragma unroll
    for (int i = 0; i < 8; ++i) { v[i] = __expf(v[i] - m); sum += v[i]; }
    sum = warp_sum(sum);
    if ((tid & 31) == 0) red[tid >> 5] = sum;
    __syncthreads();
    sum = red[0];
#pragma unroll
    for (int i = 1; i < 8; ++i) sum += red[i];

    const float inv = 1.0f / sum;
    a.x = v[0] * inv; a.y = v[1] * inv; a.z = v[2] * inv; a.w = v[3] * inv;
    b.x = v[4] * inv; b.y = v[5] * inv; b.z = v[6] * inv; b.w = v[7] * inv;
    ((float4*)p)[tid * 2]     = a;
    ((float4*)p)[tid * 2 + 1] = b;
}

extern "C" void kernel_launch(void* const* d_in, const int* in_sizes, int n_in,
                              void* d_out, int out_size)
{
    const float* x  = (const float*)d_in[0];
    const float* Wk = (const float*)d_in[1];
    const float* bk = (const float*)d_in[2];
    const float* Wq = (const float*)d_in[3];
    const float* bq = (const float*)d_in[4];
    const float* Wp = (const float*)d_in[5];
    const float* bp = (const float*)d_in[6];
    float* out = (float*)d_out;

    float *p_w2, *p_b2, *p_kq, *p_kT, *p_vals, *p_out1;
    cudaGetSymbolAddress((void**)&p_w2,   g_w2);
    cudaGetSymbolAddress((void**)&p_b2,   g_b2);
    cudaGetSymbolAddress((void**)&p_kq,   g_kq);
    cudaGetSymbolAddress((void**)&p_kT,   g_kT);
    cudaGetSymbolAddress((void**)&p_vals, g_vals);
    cudaGetSymbolAddress((void**)&p_out1, g_out1);

    // 0) stack Wk/Wq and bk/bq
    concat_w_kernel<<<(256 * 1024 + 255) / 256, 256>>>(Wk, bk, Wq, bq);

    // 1) kq[256,2048] = W2[256,1024] @ x[b] + b2
    tf32_gemm_kernel<true><<<dim3(LDIM / BN, 256 / BM, BATCH), 256>>>(
        p_w2, x, p_b2, p_kq,
        CDIM, CDIM, LDIM, LDIM,
        0LL, (long long)CDIM * LDIM, (long long)256 * LDIM);

    // 1.5) keysT[b] = keys[b]^T  -> [2048,128]
    transpose_kernel<<<dim3(LDIM / 32, ADIM / 32, BATCH), dim3(32, 8)>>>(p_kq, p_kT);

    // 2) logits[l,m] = keysT[l,:] . queries[:,m]  (M=2048, N=2048, K=128)
    tf32_gemm_kernel<false><<<dim3(LDIM / BN, LDIM / BM, BATCH), 256>>>(
        p_kT, p_kq + 128 * LDIM, nullptr, p_vals,
        ADIM, ADIM, LDIM, LDIM,
        (long long)LDIM * ADIM, (long long)256 * LDIM, (long long)LDIM * LDIM);

    // 3) softmax rows (in place), scale 1/1024
    softmax_kernel<<<BATCH * LDIM, 256>>>(p_vals);

    // 4) out1[c,m] = x[c,:] . attn[:,m]  (K=2048, dominant)
    tf32_gemm_kernel<false><<<dim3(LDIM / BN, CDIM / BM, BATCH), 256>>>(
        x, p_vals, nullptr, p_out1,
        LDIM, LDIM, LDIM, LDIM,
        (long long)CDIM * LDIM, (long long)LDIM * LDIM, (long long)CDIM * LDIM);

    // 5) out[d,m] = Wp[d,:] . out1[:,m] + bp[d]
    tf32_gemm_kernel<true><<<dim3(LDIM / BN, CDIM / BM, BATCH), 256>>>(
        Wp, p_out1, bp, out,
        CDIM, CDIM, LDIM, LDIM,
        0LL, (long long)CDIM * LDIM, (long long)CDIM * LDIM);
}

// round 4
// speedup vs baseline: 3.8665x; 1.2186x over previous
#include <cuda_runtime.h>
#include <cuda_bf16.h>
#include <cstdint>

// ---------------------------------------------------------------------------
// BasicAttention: B=8, C=1024, L=2048, A=128 — legacy tf32 mma.sync pipeline.
// All GEMM operands pre-rounded to tf32 in memory (cvt-free inner loop).
//   kq      = [Wk;Wq] @ x + [bk;bq]          (fused M=256, output rounded)
//   logits  = keysT @ queries                (K=128)
//   attn    = softmax(logits/1024)           (output rounded)
//   out1    = x @ attn                       (output rounded)
//   out     = Wp @ out1 + bp
// ---------------------------------------------------------------------------

#define BATCH 8
#define CDIM 1024
#define LDIM 2048
#define ADIM 128

__device__ float g_w2[256 * 1024];
__device__ float g_b2[256];
__device__ float g_wp[CDIM * CDIM];
__device__ float g_xr[BATCH * CDIM * LDIM];
__device__ float g_kq[BATCH * 256 * LDIM];
__device__ float g_kT[BATCH * LDIM * ADIM];
__device__ float g_vals[(long long)BATCH * LDIM * LDIM];
__device__ float g_out1[BATCH * CDIM * LDIM];

#define BM 128
#define BN 128
#define BK 32
#define AS_STRIDE 36    // row*36 + k : conflict-free fragment LDS
#define BS_STRIDE 136   // k*136 + n  : conflict-free fragment LDS

__device__ __forceinline__ float rtf(float f) {   // round to tf32, keep f32 container
    uint32_t u;
    asm("cvt.rna.tf32.f32 %0, %1;" : "=r"(u) : "f"(f));
    return __uint_as_float(u);
}

__device__ __forceinline__ void mma_tf32(float* c, const uint32_t* a, const uint32_t* b) {
    asm volatile(
        "mma.sync.aligned.m16n8k8.row.col.f32.tf32.tf32.f32 "
        "{%0,%1,%2,%3}, {%4,%5,%6,%7}, {%8,%9}, {%0,%1,%2,%3};"
        : "+f"(c[0]), "+f"(c[1]), "+f"(c[2]), "+f"(c[3])
        : "r"(a[0]), "r"(a[1]), "r"(a[2]), "r"(a[3]), "r"(b[0]), "r"(b[1]));
}

#define CP_ASYNC16(dst, src) \
    asm volatile("cp.async.cg.shared.global [%0], [%1], 16;" :: "r"(dst), "l"(src))
#define CP_COMMIT() asm volatile("cp.async.commit_group;")
#define CP_WAIT0()  asm volatile("cp.async.wait_group 0;")

// NN TF32 GEMM: C[m,n] = sum_k A[m*lda+k] * B[k*ldb+n]
// EPI: 0 none | 1 bias[row]+round | 2 round | 3 bias[row]
template <int EPI>
__global__ void __launch_bounds__(256, 2) tf32_gemm_kernel(
    const float* __restrict__ A, const float* __restrict__ B,
    const float* __restrict__ bias, float* __restrict__ C,
    int K, int lda, int ldb, int ldc,
    long long strideA, long long strideB, long long strideC)
{
    __shared__ float As[2][BM][AS_STRIDE];
    __shared__ float Bs[2][BK][BS_STRIDE];

    const int bz = blockIdx.z;
    A += (long long)bz * strideA;
    B += (long long)bz * strideB;
    C += (long long)bz * strideC;

    const int tid  = threadIdx.x;
    const int lane = tid & 31;
    const int wid  = tid >> 5;
    const int warp_m = wid >> 2;      // 0..1 -> 64-row slab
    const int warp_n = wid & 3;       // 0..3 -> 32-col slab
    const int g = lane >> 2;          // 0..7
    const int t = lane & 3;           // 0..3

    const int row0 = blockIdx.y * BM;
    const int col0 = blockIdx.x * BN;

    float acc[4][4][4];
#pragma unroll
    for (int mt = 0; mt < 4; ++mt)
#pragma unroll
        for (int nt = 0; nt < 4; ++nt)
#pragma unroll
            for (int i = 0; i < 4; ++i) acc[mt][nt][i] = 0.0f;

    const int ntiles = K / BK;

    auto issue_loads = [&](int k0, int buf) {
        // A tile: 128 rows x 32 cols = 1024 float4 chunks, 4 per thread
#pragma unroll
        for (int i = 0; i < 4; ++i) {
            int idx = i * 256 + tid;
            int r = idx >> 3, c = idx & 7;
            const float* src = A + (long long)(row0 + r) * lda + k0 + c * 4;
            uint32_t dst = (uint32_t)__cvta_generic_to_shared(&As[buf][r][c * 4]);
            CP_ASYNC16(dst, src);
        }
        // B tile: 32 rows x 128 cols = 1024 float4 chunks, 4 per thread
#pragma unroll
        for (int i = 0; i < 4; ++i) {
            int idx = i * 256 + tid;
            int r = idx >> 5, c = idx & 31;
            const float* src = B + (long long)(k0 + r) * ldb + col0 + c * 4;
            uint32_t dst = (uint32_t)__cvta_generic_to_shared(&Bs[buf][r][c * 4]);
            CP_ASYNC16(dst, src);
        }
        CP_COMMIT();
    };

    issue_loads(0, 0);
    int buf = 0;

    for (int kt = 0; kt < ntiles; ++kt) {
        CP_WAIT0();
        __syncthreads();
        if (kt + 1 < ntiles) issue_loads((kt + 1) * BK, buf ^ 1);

#pragma unroll
        for (int kk = 0; kk < BK; kk += 8) {
            uint32_t afr[4][4];
#pragma unroll
            for (int mt = 0; mt < 4; ++mt) {
                int row = warp_m * 64 + mt * 16 + g;
                afr[mt][0] = __float_as_uint(As[buf][row][kk + t]);
                afr[mt][1] = __float_as_uint(As[buf][row + 8][kk + t]);
                afr[mt][2] = __float_as_uint(As[buf][row][kk + t + 4]);
                afr[mt][3] = __float_as_uint(As[buf][row + 8][kk + t + 4]);
            }
            uint32_t bfr[4][2];
#pragma unroll
            for (int nt = 0; nt < 4; ++nt) {
                int cn = warp_n * 32 + nt * 8 + g;
                bfr[nt][0] = __float_as_uint(Bs[buf][kk + t][cn]);
                bfr[nt][1] = __float_as_uint(Bs[buf][kk + t + 4][cn]);
            }
#pragma unroll
            for (int mt = 0; mt < 4; ++mt)
#pragma unroll
                for (int nt = 0; nt < 4; ++nt)
                    mma_tf32(acc[mt][nt], afr[mt], bfr[nt]);
        }
        __syncthreads();
        buf ^= 1;
    }

    // Epilogue: c0 (g,2t) c1 (g,2t+1) c2 (g+8,2t) c3 (g+8,2t+1)
#pragma unroll
    for (int mt = 0; mt < 4; ++mt) {
        int rowA = row0 + warp_m * 64 + mt * 16 + g;
        float bv0 = (EPI == 1 || EPI == 3) ? bias[rowA] : 0.0f;
        float bv1 = (EPI == 1 || EPI == 3) ? bias[rowA + 8] : 0.0f;
#pragma unroll
        for (int nt = 0; nt < 4; ++nt) {
            int col = col0 + warp_n * 32 + nt * 8 + 2 * t;
            float o0 = acc[mt][nt][0] + bv0, o1 = acc[mt][nt][1] + bv0;
            float o2 = acc[mt][nt][2] + bv1, o3 = acc[mt][nt][3] + bv1;
            if (EPI == 1 || EPI == 2) {
                o0 = rtf(o0); o1 = rtf(o1); o2 = rtf(o2); o3 = rtf(o3);
            }
            float2 v0 = { o0, o1 };
            float2 v1 = { o2, o3 };
            *(float2*)(C + (long long)rowA * ldc + col)       = v0;
            *(float2*)(C + (long long)(rowA + 8) * ldc + col) = v1;
        }
    }
}

// ---------------- helpers ----------------

__global__ void concat_w_kernel(const float* __restrict__ Wk, const float* __restrict__ bk,
                                const float* __restrict__ Wq, const float* __restrict__ bq)
{
    int i = blockIdx.x * blockDim.x + threadIdx.x;
    const int half = 128 * 1024;
    if (i < half)          g_w2[i] = rtf(Wk[i]);
    else if (i < 2 * half) g_w2[i] = rtf(Wq[i - half]);
    if (i < 128)           g_b2[i] = bk[i];
    else if (i < 256)      g_b2[i] = bq[i - 128];
}

__global__ void round_wp_kernel(const float* __restrict__ Wp)
{
    int i = blockIdx.x * blockDim.x + threadIdx.x;
    if (i < CDIM * CDIM) g_wp[i] = rtf(Wp[i]);
}

// x rounded copy (float4 granularity)
__global__ void __launch_bounds__(256) round_x_kernel(const float* __restrict__ x)
{
    long long i4 = (long long)blockIdx.x * blockDim.x + threadIdx.x;
    float4 v = ((const float4*)x)[i4];
    v.x = rtf(v.x); v.y = rtf(v.y); v.z = rtf(v.z); v.w = rtf(v.w);
    ((float4*)g_xr)[i4] = v;
}

// keys [B,128,2048] -> keysT [B,2048,128]
__global__ void transpose_kernel(const float* __restrict__ in, float* __restrict__ outp)
{
    __shared__ float tile[32][33];
    const int bz = blockIdx.z;
    in   += (long long)bz * 256 * LDIM;
    outp += (long long)bz * LDIM * ADIM;

    int x = blockIdx.x * 32 + threadIdx.x;
    int y = blockIdx.y * 32 + threadIdx.y;
#pragma unroll
    for (int j = 0; j < 32; j += 8)
        tile[threadIdx.y + j][threadIdx.x] = in[(long long)(y + j) * LDIM + x];
    __syncthreads();
    int x2 = blockIdx.y * 32 + threadIdx.x;
    int y2 = blockIdx.x * 32 + threadIdx.y;
#pragma unroll
    for (int j = 0; j < 32; j += 8)
        outp[(long long)(y2 + j) * ADIM + x2] = tile[threadIdx.x][threadIdx.y + j];
}

__device__ __forceinline__ float warp_max(float v) {
#pragma unroll
    for (int o = 16; o > 0; o >>= 1) v = fmaxf(v, __shfl_xor_sync(0xffffffffu, v, o));
    return v;
}
__device__ __forceinline__ float warp_sum(float v) {
#pragma unroll
    for (int o = 16; o > 0; o >>= 1) v += __shfl_xor_sync(0xffffffffu, v, o);
    return v;
}

// In-place row softmax of logits/1024 (rows of 2048), output rounded to tf32.
__global__ void __launch_bounds__(256) softmax_kernel(float* __restrict__ V)
{
    float* p = V + (long long)blockIdx.x * LDIM;
    const int tid = threadIdx.x;

    float4 a = ((const float4*)p)[tid * 2];
    float4 b = ((const float4*)p)[tid * 2 + 1];
    const float s = 1.0f / 1024.0f;
    float v[8] = { a.x * s, a.y * s, a.z * s, a.w * s,
                   b.x * s, b.y * s, b.z * s, b.w * s };

    float m = v[0];
#pragma unroll
    for (int i = 1; i < 8; ++i) m = fmaxf(m, v[i]);
    m = warp_max(m);

    __shared__ float red[8];
    if ((tid & 31) == 0) red[tid >> 5] = m;
    __syncthreads();
    m = red[0];
#pragma unroll
    for (int i = 1; i < 8; ++i) m = fmaxf(m, red[i]);
    __syncthreads();

    float sum = 0.0f;
#pragma unroll
    for (int i = 0; i < 8; ++i) { v[i] = __expf(v[i] - m); sum += v[i]; }
    sum = warp_sum(sum);
    if ((tid & 31) == 0) red[tid >> 5] = sum;
    __syncthreads();
    sum = red[0];
#pragma unroll
    for (int i = 1; i < 8; ++i) sum += red[i];

    const float inv = 1.0f / sum;
    a.x = rtf(v[0] * inv); a.y = rtf(v[1] * inv); a.z = rtf(v[2] * inv); a.w = rtf(v[3] * inv);
    b.x = rtf(v[4] * inv); b.y = rtf(v[5] * inv); b.z = rtf(v[6] * inv); b.w = rtf(v[7] * inv);
    ((float4*)p)[tid * 2]     = a;
    ((float4*)p)[tid * 2 + 1] = b;
}

extern "C" void kernel_launch(void* const* d_in, const int* in_sizes, int n_in,
                              void* d_out, int out_size)
{
    const float* x  = (const float*)d_in[0];
    const float* Wk = (const float*)d_in[1];
    const float* bk = (const float*)d_in[2];
    const float* Wq = (const float*)d_in[3];
    const float* bq = (const float*)d_in[4];
    const float* Wp = (const float*)d_in[5];
    const float* bp = (const float*)d_in[6];
    float* out = (float*)d_out;

    float *p_w2, *p_b2, *p_wp, *p_xr, *p_kq, *p_kT, *p_vals, *p_out1;
    cudaGetSymbolAddress((void**)&p_w2,   g_w2);
    cudaGetSymbolAddress((void**)&p_b2,   g_b2);
    cudaGetSymbolAddress((void**)&p_wp,   g_wp);
    cudaGetSymbolAddress((void**)&p_xr,   g_xr);
    cudaGetSymbolAddress((void**)&p_kq,   g_kq);
    cudaGetSymbolAddress((void**)&p_kT,   g_kT);
    cudaGetSymbolAddress((void**)&p_vals, g_vals);
    cudaGetSymbolAddress((void**)&p_out1, g_out1);

    // 0) operand prep: rounded weights + rounded x
    concat_w_kernel<<<(256 * 1024 + 255) / 256, 256>>>(Wk, bk, Wq, bq);
    round_wp_kernel<<<(CDIM * CDIM + 255) / 256, 256>>>(Wp);
    round_x_kernel<<<(BATCH * CDIM * LDIM / 4) / 256, 256>>>(x);

    // 1) kq[256,2048] = W2 @ xr + b2   (bias + round)
    tf32_gemm_kernel<1><<<dim3(LDIM / BN, 256 / BM, BATCH), 256>>>(
        p_w2, p_xr, p_b2, p_kq,
        CDIM, CDIM, LDIM, LDIM,
        0LL, (long long)CDIM * LDIM, (long long)256 * LDIM);

    // 1.5) keysT = keys^T
    transpose_kernel<<<dim3(LDIM / 32, ADIM / 32, BATCH), dim3(32, 8)>>>(p_kq, p_kT);

    // 2) logits = keysT @ queries  (K=128)
    tf32_gemm_kernel<0><<<dim3(LDIM / BN, LDIM / BM, BATCH), 256>>>(
        p_kT, p_kq + 128 * LDIM, nullptr, p_vals,
        ADIM, ADIM, LDIM, LDIM,
        (long long)LDIM * ADIM, (long long)256 * LDIM, (long long)LDIM * LDIM);

    // 3) softmax (in place, rounds output)
    softmax_kernel<<<BATCH * LDIM, 256>>>(p_vals);

    // 4) out1 = xr @ attn  (round)
    tf32_gemm_kernel<2><<<dim3(LDIM / BN, CDIM / BM, BATCH), 256>>>(
        p_xr, p_vals, nullptr, p_out1,
        LDIM, LDIM, LDIM, LDIM,
        (long long)CDIM * LDIM, (long long)LDIM * LDIM, (long long)CDIM * LDIM);

    // 5) out = Wp @ out1 + bp
    tf32_gemm_kernel<3><<<dim3(LDIM / BN, CDIM / BM, BATCH), 256>>>(
        p_wp, p_out1, bp, out,
        CDIM, CDIM, LDIM, LDIM,
        0LL, (long long)CDIM * LDIM, (long long)CDIM * LDIM);
}

// round 5
// speedup vs baseline: 6.6270x; 1.7139x over previous
#include <cuda_runtime.h>
#include <cuda_fp16.h>
#include <cstdint>

// ---------------------------------------------------------------------------
// BasicAttention B=8, C=1024, L=2048, A=128 — fp16 mma.m16n8k16 pipeline.
// All GEMMs in K-major TN form: D[i,j] = sum_k A[i,k] * B[j,k], operands half.
//   kqT  [2048,256]  = xT_h · W2_h^T + b2(col)      (keysT cols 0:128, queriesT 128:256)
//   vals [2048,2048] = exp((keysT_rows · queriesT_rows^T)/1024)  (f32, exp in epilogue)
//   rcp[l] = 1/rowsum(vals[l,:]);  attnT[m,l] = half(vals[l,m]*rcp[l])  (fused transpose)
//   out1T[2048,1024] = attnT · x_h^T                (half)
//   out  [1024,2048] = Wp_h · out1T^T + bp(row)     (f32)
// ---------------------------------------------------------------------------

#define BATCH 8
#define CDIM 1024
#define LDIM 2048

__device__ __half g_w2h[256 * 1024];
__device__ float  g_b2[256];
__device__ __half g_wph[CDIM * CDIM];
__device__ __half g_xh[BATCH * CDIM * LDIM];     // x rounded, [C][L]
__device__ __half g_xTh[BATCH * LDIM * CDIM];    // x transposed rounded, [L][C]
__device__ __half g_kqT[BATCH * LDIM * 256];
__device__ float  g_vals[(long long)BATCH * LDIM * LDIM];
__device__ float  g_rcp[BATCH * LDIM];
__device__ __half g_attnT[(long long)BATCH * LDIM * LDIM];
__device__ __half g_out1T[BATCH * LDIM * CDIM];

#define BM 128
#define BN 128
#define BK 64
#define KSTRIDE 72                       // halves per smem row (conflict-free)
#define TILE_HALVES (128 * KSTRIDE)      // 9216 halves per tile per buf

#define CP_ASYNC16(dst, src) \
    asm volatile("cp.async.cg.shared.global [%0], [%1], 16;" :: "r"(dst), "l"(src))
#define CP_COMMIT() asm volatile("cp.async.commit_group;")
#define CP_WAIT0()  asm volatile("cp.async.wait_group 0;")

#define LDSM4(r0, r1, r2, r3, addr) \
    asm volatile("ldmatrix.sync.aligned.m8n8.x4.shared.b16 {%0,%1,%2,%3}, [%4];" \
                 : "=r"(r0), "=r"(r1), "=r"(r2), "=r"(r3) : "r"(addr))

__device__ __forceinline__ void mma_f16(float* c, const uint32_t* a, const uint32_t* b) {
    asm volatile(
        "mma.sync.aligned.m16n8k16.row.col.f32.f16.f16.f32 "
        "{%0,%1,%2,%3}, {%4,%5,%6,%7}, {%8,%9}, {%0,%1,%2,%3};"
        : "+f"(c[0]), "+f"(c[1]), "+f"(c[2]), "+f"(c[3])
        : "r"(a[0]), "r"(a[1]), "r"(a[2]), "r"(a[3]), "r"(b[0]), "r"(b[1]));
}

// TN fp16 GEMM: D[i,j] = sum_k A[i*lda+k] * B[j*ldb+k]
// EPI: 0 -> half out | 1 -> half out + bias[col] | 2 -> f32 out = exp(v/1024) | 3 -> f32 out + bias[row]
template <int EPI, typename OT>
__global__ void __launch_bounds__(256, 2) hgemm_kernel(
    const __half* __restrict__ A, const __half* __restrict__ B,
    const float* __restrict__ bias, OT* __restrict__ C,
    int K, int lda, int ldb, int ldc,
    long long sA, long long sB, long long sC)
{
    extern __shared__ __half sm[];
    __half* As = sm;                          // [2][128][KSTRIDE]
    __half* Bs = sm + 2 * TILE_HALVES;        // [2][128][KSTRIDE]

    const int bz = blockIdx.z;
    A += (long long)bz * sA;
    B += (long long)bz * sB;
    C += (long long)bz * sC;

    const int tid  = threadIdx.x;
    const int lane = tid & 31;
    const int wid  = tid >> 5;
    const int warp_m = wid >> 2;              // 0..1 -> 64-row slab
    const int warp_n = wid & 3;               // 0..3 -> 32-col slab
    const int g = lane >> 2;
    const int t = lane & 3;

    const int row0 = blockIdx.y * BM;
    const int col0 = blockIdx.x * BN;

    const uint32_t asb = (uint32_t)__cvta_generic_to_shared(As);
    const uint32_t bsb = (uint32_t)__cvta_generic_to_shared(Bs);

    // ldmatrix per-lane offsets (halves)
    const int aRow = warp_m * 64 + ((lane >> 3) & 1) * 8 + (lane & 7);
    const int aK   = ((lane >> 4) & 1) * 8;
    const int bRow = warp_n * 32 + ((lane >> 4) & 1) * 8 + (lane & 7);
    const int bK   = ((lane >> 3) & 1) * 8;

    float acc[4][4][4];
#pragma unroll
    for (int mt = 0; mt < 4; ++mt)
#pragma unroll
        for (int nt = 0; nt < 4; ++nt)
#pragma unroll
            for (int i = 0; i < 4; ++i) acc[mt][nt][i] = 0.0f;

    const int ntiles = K / BK;

    auto issue_loads = [&](int k0, int buf) {
        const uint32_t ab = asb + (uint32_t)(buf * TILE_HALVES) * 2;
        const uint32_t bb = bsb + (uint32_t)(buf * TILE_HALVES) * 2;
#pragma unroll
        for (int i = 0; i < 4; ++i) {     // A: 128 rows x 8 chunks of 8 halves
            int idx = i * 256 + tid;
            int r = idx >> 3, c = idx & 7;
            const __half* src = A + (long long)(row0 + r) * lda + k0 + c * 8;
            CP_ASYNC16(ab + (uint32_t)(r * KSTRIDE + c * 8) * 2, src);
        }
#pragma unroll
        for (int i = 0; i < 4; ++i) {     // B: 128 rows x 8 chunks
            int idx = i * 256 + tid;
            int r = idx >> 3, c = idx & 7;
            const __half* src = B + (long long)(col0 + r) * ldb + k0 + c * 8;
            CP_ASYNC16(bb + (uint32_t)(r * KSTRIDE + c * 8) * 2, src);
        }
        CP_COMMIT();
    };

    issue_loads(0, 0);
    int buf = 0;

    for (int kt = 0; kt < ntiles; ++kt) {
        CP_WAIT0();
        __syncthreads();
        if (kt + 1 < ntiles) issue_loads((kt + 1) * BK, buf ^ 1);

        const uint32_t ab = asb + (uint32_t)(buf * TILE_HALVES) * 2;
        const uint32_t bb = bsb + (uint32_t)(buf * TILE_HALVES) * 2;

#pragma unroll
        for (int ks = 0; ks < BK / 16; ++ks) {
            const int kk = ks * 16;
            uint32_t af[4][4];
#pragma unroll
            for (int mt = 0; mt < 4; ++mt) {
                uint32_t addr = ab + (uint32_t)((aRow + mt * 16) * KSTRIDE + kk + aK) * 2;
                LDSM4(af[mt][0], af[mt][1], af[mt][2], af[mt][3], addr);
            }
            uint32_t bf[4][2];
#pragma unroll
            for (int p = 0; p < 2; ++p) {  // pair of 16-col n-slices -> 4 nt frags
                uint32_t addr = bb + (uint32_t)((bRow + p * 16) * KSTRIDE + kk + bK) * 2;
                LDSM4(bf[2 * p][0], bf[2 * p][1], bf[2 * p + 1][0], bf[2 * p + 1][1], addr);
            }
#pragma unroll
            for (int mt = 0; mt < 4; ++mt)
#pragma unroll
                for (int nt = 0; nt < 4; ++nt)
                    mma_f16(acc[mt][nt], af[mt], bf[nt]);
        }
        __syncthreads();
        buf ^= 1;
    }

    // Epilogue: c0 (g,2t) c1 (g,2t+1) c2 (g+8,2t) c3 (g+8,2t+1)
#pragma unroll
    for (int mt = 0; mt < 4; ++mt) {
        const int rowA = row0 + warp_m * 64 + mt * 16 + g;
        float br0 = 0.f, br1 = 0.f;
        if (EPI == 3) { br0 = bias[rowA]; br1 = bias[rowA + 8]; }
#pragma unroll
        for (int nt = 0; nt < 4; ++nt) {
            const int col = col0 + warp_n * 32 + nt * 8 + 2 * t;
            float c0 = acc[mt][nt][0], c1 = acc[mt][nt][1];
            float c2 = acc[mt][nt][2], c3 = acc[mt][nt][3];
            if (EPI == 1) {
                float b0 = bias[col], b1 = bias[col + 1];
                c0 += b0; c1 += b1; c2 += b0; c3 += b1;
            } else if (EPI == 2) {
                const float s = 1.0f / 1024.0f;
                c0 = __expf(c0 * s); c1 = __expf(c1 * s);
                c2 = __expf(c2 * s); c3 = __expf(c3 * s);
            } else if (EPI == 3) {
                c0 += br0; c1 += br0; c2 += br1; c3 += br1;
            }
            if (sizeof(OT) == 2) {
                __half2* p0 = (__half2*)((__half*)C + (long long)rowA * ldc + col);
                __half2* p1 = (__half2*)((__half*)C + (long long)(rowA + 8) * ldc + col);
                *p0 = __floats2half2_rn(c0, c1);
                *p1 = __floats2half2_rn(c2, c3);
            } else {
                float2 v0 = { c0, c1 };
                float2 v1 = { c2, c3 };
                *(float2*)((float*)C + (long long)rowA * ldc + col) = v0;
                *(float2*)((float*)C + (long long)(rowA + 8) * ldc + col) = v1;
            }
        }
    }
}

// ---------------- prep / softmax kernels ----------------

__global__ void concat_w_kernel(const float* __restrict__ Wk, const float* __restrict__ bk,
                                const float* __restrict__ Wq, const float* __restrict__ bq)
{
    int i = blockIdx.x * blockDim.x + threadIdx.x;
    const int half_n = 128 * 1024;
    if (i < half_n)          g_w2h[i] = __float2half_rn(Wk[i]);
    else if (i < 2 * half_n) g_w2h[i] = __float2half_rn(Wq[i - half_n]);
    if (i < 128)             g_b2[i] = bk[i];
    else if (i < 256)        g_b2[i] = bq[i - 128];
}

__global__ void round_wp_kernel(const float* __restrict__ Wp)
{
    int i = blockIdx.x * blockDim.x + threadIdx.x;
    if (i < CDIM * CDIM) g_wph[i] = __float2half_rn(Wp[i]);
}

// x [B,1024,2048] f32 -> g_xh half (same layout) + g_xTh half (transposed)
__global__ void xprep_kernel(const float* __restrict__ x)
{
    __shared__ float tile[32][33];
    const int bz = blockIdx.z;
    const float* in = x + (long long)bz * CDIM * LDIM;
    __half* xh  = g_xh  + (long long)bz * CDIM * LDIM;
    __half* xth = g_xTh + (long long)bz * LDIM * CDIM;

    int l = blockIdx.x * 32 + threadIdx.x;
    int c = blockIdx.y * 32 + threadIdx.y;
#pragma unroll
    for (int j = 0; j < 32; j += 8) {
        float v = in[(long long)(c + j) * LDIM + l];
        xh[(long long)(c + j) * LDIM + l] = __float2half_rn(v);
        tile[threadIdx.y + j][threadIdx.x] = v;
    }
    __syncthreads();
    int c2 = blockIdx.y * 32 + threadIdx.x;
    int l2 = blockIdx.x * 32 + threadIdx.y;
#pragma unroll
    for (int j = 0; j < 32; j += 8)
        xth[(long long)(l2 + j) * CDIM + c2] = __float2half_rn(tile[threadIdx.x][threadIdx.y + j]);
}

__device__ __forceinline__ float warp_sum(float v) {
#pragma unroll
    for (int o = 16; o > 0; o >>= 1) v += __shfl_xor_sync(0xffffffffu, v, o);
    return v;
}

// one block per row: rcp[row] = 1 / sum(vals[row,:])
__global__ void __launch_bounds__(256) rowsum_kernel()
{
    const long long row = blockIdx.x;
    const float* p = g_vals + row * LDIM;
    const int tid = threadIdx.x;
    float4 a = ((const float4*)p)[tid * 2];
    float4 b = ((const float4*)p)[tid * 2 + 1];
    float s = a.x + a.y + a.z + a.w + b.x + b.y + b.z + b.w;
    s = warp_sum(s);
    __shared__ float red[8];
    if ((tid & 31) == 0) red[tid >> 5] = s;
    __syncthreads();
    if (tid == 0) {
        float tot = red[0];
#pragma unroll
        for (int i = 1; i < 8; ++i) tot += red[i];
        g_rcp[row] = 1.0f / tot;
    }
}

// attnT[m,l] = half(vals[l,m] * rcp[l])  — 64x64 tiles
__global__ void __launch_bounds__(512) transpose_norm_kernel()
{
    __shared__ float tile[64][65];
    const int bz = blockIdx.z;
    const float*  V = g_vals  + (long long)bz * LDIM * LDIM;
    __half*       T = g_attnT + (long long)bz * LDIM * LDIM;
    const float*  R = g_rcp + bz * LDIM;

    const int tx = threadIdx.x;        // 0..63
    const int ty = threadIdx.y;        // 0..7
    const int m0 = blockIdx.x * 64;
    const int l0 = blockIdx.y * 64;

#pragma unroll
    for (int j = 0; j < 64; j += 8) {
        int l = l0 + ty + j;
        tile[ty + j][tx] = V[(long long)l * LDIM + m0 + tx] * R[l];
    }
    __syncthreads();
#pragma unroll
    for (int j = 0; j < 64; j += 8) {
        int m = m0 + ty + j;
        T[(long long)m * LDIM + l0 + tx] = __float2half_rn(tile[tx][ty + j]);
    }
}

extern "C" void kernel_launch(void* const* d_in, const int* in_sizes, int n_in,
                              void* d_out, int out_size)
{
    const float* x  = (const float*)d_in[0];
    const float* Wk = (const float*)d_in[1];
    const float* bk = (const float*)d_in[2];
    const float* Wq = (const float*)d_in[3];
    const float* bq = (const float*)d_in[4];
    const float* Wp = (const float*)d_in[5];
    const float* bp = (const float*)d_in[6];
    float* out = (float*)d_out;

    const int SMEM = 4 * TILE_HALVES * 2;   // 73728 bytes
    cudaFuncSetAttribute(hgemm_kernel<0, __half>, cudaFuncAttributeMaxDynamicSharedMemorySize, SMEM);
    cudaFuncSetAttribute(hgemm_kernel<1, __half>, cudaFuncAttributeMaxDynamicSharedMemorySize, SMEM);
    cudaFuncSetAttribute(hgemm_kernel<2, float>,  cudaFuncAttributeMaxDynamicSharedMemorySize, SMEM);
    cudaFuncSetAttribute(hgemm_kernel<3, float>,  cudaFuncAttributeMaxDynamicSharedMemorySize, SMEM);

    __half *p_w2h, *p_wph, *p_xh, *p_xTh, *p_kqT, *p_attnT, *p_out1T;
    float *p_b2, *p_vals;
    cudaGetSymbolAddress((void**)&p_w2h,   g_w2h);
    cudaGetSymbolAddress((void**)&p_b2,    g_b2);
    cudaGetSymbolAddress((void**)&p_wph,   g_wph);
    cudaGetSymbolAddress((void**)&p_xh,    g_xh);
    cudaGetSymbolAddress((void**)&p_xTh,   g_xTh);
    cudaGetSymbolAddress((void**)&p_kqT,   g_kqT);
    cudaGetSymbolAddress((void**)&p_vals,  g_vals);
    cudaGetSymbolAddress((void**)&p_attnT, g_attnT);
    cudaGetSymbolAddress((void**)&p_out1T, g_out1T);

    // 0) operand prep
    concat_w_kernel<<<(256 * 1024 + 255) / 256, 256>>>(Wk, bk, Wq, bq);
    round_wp_kernel<<<(CDIM * CDIM + 255) / 256, 256>>>(Wp);
    xprep_kernel<<<dim3(LDIM / 32, CDIM / 32, BATCH), dim3(32, 8)>>>(x);

    // 1) kqT[2048,256] = xT_h . W2_h^T + b2(col)
    hgemm_kernel<1, __half><<<dim3(256 / BN, LDIM / BM, BATCH), 256, SMEM>>>(
        p_xTh, p_w2h, p_b2, p_kqT,
        CDIM, CDIM, CDIM, 256,
        (long long)LDIM * CDIM, 0LL, (long long)LDIM * 256);

    // 2) vals[l,m] = exp((keysT[l,:].queriesT[m,:])/1024)   K=128
    hgemm_kernel<2, float><<<dim3(LDIM / BN, LDIM / BM, BATCH), 256, SMEM>>>(
        p_kqT, p_kqT + 128, nullptr, p_vals,
        128, 256, 256, LDIM,
        (long long)LDIM * 256, (long long)LDIM * 256, (long long)LDIM * LDIM);

    // 3) row sums -> rcp; fused transpose+normalize -> attnT (half)
    rowsum_kernel<<<BATCH * LDIM, 256>>>();
    transpose_norm_kernel<<<dim3(LDIM / 64, LDIM / 64, BATCH), dim3(64, 8)>>>();

    // 4) out1T[m,c] = attnT[m,:] . x_h[c,:]   K=2048 (dominant)
    hgemm_kernel<0, __half><<<dim3(CDIM / BN, LDIM / BM, BATCH), 256, SMEM>>>(
        p_attnT, p_xh, nullptr, p_out1T,
        LDIM, LDIM, LDIM, CDIM,
        (long long)LDIM * LDIM, (long long)CDIM * LDIM, (long long)LDIM * CDIM);

    // 5) out[d,m] = Wp_h[d,:] . out1T[m,:] + bp[d]   K=1024
    hgemm_kernel<3, float><<<dim3(LDIM / BN, CDIM / BM, BATCH), 256, SMEM>>>(
        p_wph, p_out1T, bp, out,
        CDIM, CDIM, CDIM, LDIM,
        0LL, (long long)LDIM * CDIM, (long long)CDIM * LDIM);
}

// round 6
// speedup vs baseline: 7.3253x; 1.1054x over previous
#include <cuda_runtime.h>
#include <cuda_fp16.h>
#include <cstdint>

// ---------------------------------------------------------------------------
// BasicAttention B=8, C=1024, L=2048, A=128 — fp16 mma.m16n8k16, restructured:
//   xTh  [2048,1024] = half(x^T)
//   kqT  [2048,256]  = xTh · W2^T + b2(col)       (keysT 0:128, queriesT 128:256)
//   E2   [2048,2048] = exp((qT_m · kT_l)/1024)    half, layout [m][l]  (= attnT unnorm)
//   rcp[l] = 1 / sum_m E2[m,l]                    (column sums)
//   y'   [1024,2048] = (Wp · x)[d,l] * rcp[l]     half (norm folded into epilogue)
//   out  [1024,2048] = y' · E2^T + bp(row)        f32
// All GEMMs TN K-major: D[i,j] = sum_k A[i,k]*B[j,k].
// ---------------------------------------------------------------------------

#define BATCH 8
#define CDIM 1024
#define LDIM 2048

__device__ __half g_w2h[256 * 1024];
__device__ float  g_b2[256];
__device__ __half g_wph[CDIM * CDIM];
__device__ __half g_xTh[BATCH * LDIM * CDIM];
__device__ __half g_kqT[BATCH * LDIM * 256];
__device__ __half g_E2[(long long)BATCH * LDIM * LDIM];
__device__ float  g_part[BATCH * 16 * LDIM];
__device__ float  g_rcp[BATCH * LDIM];
__device__ __half g_y[BATCH * CDIM * LDIM];

#define BM 128
#define BN 128
#define BK 64
#define KSTRIDE 72
#define TILE_HALVES (128 * KSTRIDE)

#define CP_ASYNC16(dst, src) \
    asm volatile("cp.async.cg.shared.global [%0], [%1], 16;" :: "r"(dst), "l"(src))
#define CP_COMMIT() asm volatile("cp.async.commit_group;")
#define CP_WAIT0()  asm volatile("cp.async.wait_group 0;")

#define LDSM4(r0, r1, r2, r3, addr) \
    asm volatile("ldmatrix.sync.aligned.m8n8.x4.shared.b16 {%0,%1,%2,%3}, [%4];" \
                 : "=r"(r0), "=r"(r1), "=r"(r2), "=r"(r3) : "r"(addr))

__device__ __forceinline__ void mma_f16(float* c, const uint32_t* a, const uint32_t* b) {
    asm volatile(
        "mma.sync.aligned.m16n8k16.row.col.f32.f16.f16.f32 "
        "{%0,%1,%2,%3}, {%4,%5,%6,%7}, {%8,%9}, {%0,%1,%2,%3};"
        : "+f"(c[0]), "+f"(c[1]), "+f"(c[2]), "+f"(c[3])
        : "r"(a[0]), "r"(a[1]), "r"(a[2]), "r"(a[3]), "r"(b[0]), "r"(b[1]));
}

// TN fp16 GEMM. EPI: 1 half+bias[col] | 2 half=exp(v/1024) | 3 f32+bias[row] | 4 half*scale[col] (per-batch)
template <int EPI, typename OT>
__global__ void __launch_bounds__(256, 2) hgemm_kernel(
    const __half* __restrict__ A, const __half* __restrict__ B,
    const float* __restrict__ bias, OT* __restrict__ C,
    int K, int lda, int ldb, int ldc,
    long long sA, long long sB, long long sC)
{
    extern __shared__ __half sm[];
    __half* As = sm;
    __half* Bs = sm + 2 * TILE_HALVES;

    const int bz = blockIdx.z;
    A += (long long)bz * sA;
    B += (long long)bz * sB;
    C += (long long)bz * sC;
    if (EPI == 4) bias += (long long)bz * LDIM;   // per-batch rcp

    const int tid  = threadIdx.x;
    const int lane = tid & 31;
    const int wid  = tid >> 5;
    const int warp_m = wid >> 2;
    const int warp_n = wid & 3;
    const int g = lane >> 2;
    const int t = lane & 3;

    const int row0 = blockIdx.y * BM;
    const int col0 = blockIdx.x * BN;

    const uint32_t asb = (uint32_t)__cvta_generic_to_shared(As);
    const uint32_t bsb = (uint32_t)__cvta_generic_to_shared(Bs);

    const int aRow = warp_m * 64 + ((lane >> 3) & 1) * 8 + (lane & 7);
    const int aK   = ((lane >> 4) & 1) * 8;
    const int bRow = warp_n * 32 + ((lane >> 4) & 1) * 8 + (lane & 7);
    const int bK   = ((lane >> 3) & 1) * 8;

    float acc[4][4][4];
#pragma unroll
    for (int mt = 0; mt < 4; ++mt)
#pragma unroll
        for (int nt = 0; nt < 4; ++nt)
#pragma unroll
            for (int i = 0; i < 4; ++i) acc[mt][nt][i] = 0.0f;

    const int ntiles = K / BK;

    auto issue_loads = [&](int k0, int buf) {
        const uint32_t ab = asb + (uint32_t)(buf * TILE_HALVES) * 2;
        const uint32_t bb = bsb + (uint32_t)(buf * TILE_HALVES) * 2;
#pragma unroll
        for (int i = 0; i < 4; ++i) {
            int idx = i * 256 + tid;
            int r = idx >> 3, c = idx & 7;
            const __half* src = A + (long long)(row0 + r) * lda + k0 + c * 8;
            CP_ASYNC16(ab + (uint32_t)(r * KSTRIDE + c * 8) * 2, src);
        }
#pragma unroll
        for (int i = 0; i < 4; ++i) {
            int idx = i * 256 + tid;
            int r = idx >> 3, c = idx & 7;
            const __half* src = B + (long long)(col0 + r) * ldb + k0 + c * 8;
            CP_ASYNC16(bb + (uint32_t)(r * KSTRIDE + c * 8) * 2, src);
        }
        CP_COMMIT();
    };

    issue_loads(0, 0);
    int buf = 0;

    for (int kt = 0; kt < ntiles; ++kt) {
        CP_WAIT0();
        __syncthreads();
        if (kt + 1 < ntiles) issue_loads((kt + 1) * BK, buf ^ 1);

        const uint32_t ab = asb + (uint32_t)(buf * TILE_HALVES) * 2;
        const uint32_t bb = bsb + (uint32_t)(buf * TILE_HALVES) * 2;

#pragma unroll
        for (int ks = 0; ks < BK / 16; ++ks) {
            const int kk = ks * 16;
            uint32_t af[4][4];
#pragma unroll
            for (int mt = 0; mt < 4; ++mt) {
                uint32_t addr = ab + (uint32_t)((aRow + mt * 16) * KSTRIDE + kk + aK) * 2;
                LDSM4(af[mt][0], af[mt][1], af[mt][2], af[mt][3], addr);
            }
            uint32_t bf[4][2];
#pragma unroll
            for (int p = 0; p < 2; ++p) {
                uint32_t addr = bb + (uint32_t)((bRow + p * 16) * KSTRIDE + kk + bK) * 2;
                LDSM4(bf[2 * p][0], bf[2 * p][1], bf[2 * p + 1][0], bf[2 * p + 1][1], addr);
            }
#pragma unroll
            for (int mt = 0; mt < 4; ++mt)
#pragma unroll
                for (int nt = 0; nt < 4; ++nt)
                    mma_f16(acc[mt][nt], af[mt], bf[nt]);
        }
        __syncthreads();
        buf ^= 1;
    }

#pragma unroll
    for (int mt = 0; mt < 4; ++mt) {
        const int rowA = row0 + warp_m * 64 + mt * 16 + g;
        float br0 = 0.f, br1 = 0.f;
        if (EPI == 3) { br0 = bias[rowA]; br1 = bias[rowA + 8]; }
#pragma unroll
        for (int nt = 0; nt < 4; ++nt) {
            const int col = col0 + warp_n * 32 + nt * 8 + 2 * t;
            float c0 = acc[mt][nt][0], c1 = acc[mt][nt][1];
            float c2 = acc[mt][nt][2], c3 = acc[mt][nt][3];
            if (EPI == 1) {
                float b0 = bias[col], b1 = bias[col + 1];
                c0 += b0; c1 += b1; c2 += b0; c3 += b1;
            } else if (EPI == 2) {
                const float s = 1.0f / 1024.0f;
                c0 = __expf(c0 * s); c1 = __expf(c1 * s);
                c2 = __expf(c2 * s); c3 = __expf(c3 * s);
            } else if (EPI == 3) {
                c0 += br0; c1 += br0; c2 += br1; c3 += br1;
            } else if (EPI == 4) {
                float s0 = bias[col], s1 = bias[col + 1];
                c0 *= s0; c1 *= s1; c2 *= s0; c3 *= s1;
            }
            if (sizeof(OT) == 2) {
                __half2* p0 = (__half2*)((__half*)C + (long long)rowA * ldc + col);
                __half2* p1 = (__half2*)((__half*)C + (long long)(rowA + 8) * ldc + col);
                *p0 = __floats2half2_rn(c0, c1);
                *p1 = __floats2half2_rn(c2, c3);
            } else {
                float2 v0 = { c0, c1 };
                float2 v1 = { c2, c3 };
                *(float2*)((float*)C + (long long)rowA * ldc + col) = v0;
                *(float2*)((float*)C + (long long)(rowA + 8) * ldc + col) = v1;
            }
        }
    }
}

// ---------------- prep / reduction kernels ----------------

__global__ void concat_w_kernel(const float* __restrict__ Wk, const float* __restrict__ bk,
                                const float* __restrict__ Wq, const float* __restrict__ bq)
{
    int i = blockIdx.x * blockDim.x + threadIdx.x;
    const int half_n = 128 * 1024;
    if (i < half_n)          g_w2h[i] = __float2half_rn(Wk[i]);
    else if (i < 2 * half_n) g_w2h[i] = __float2half_rn(Wq[i - half_n]);
    if (i < 128)             g_b2[i] = bk[i];
    else if (i < 256)        g_b2[i] = bq[i - 128];
}

__global__ void round_wp_kernel(const float* __restrict__ Wp)
{
    int i = blockIdx.x * blockDim.x + threadIdx.x;
    if (i < CDIM * CDIM) g_wph[i] = __float2half_rn(Wp[i]);
}

// x [B,1024,2048] f32 -> xTh [B,2048,1024] half
__global__ void xprep_kernel(const float* __restrict__ x)
{
    __shared__ float tile[32][33];
    const int bz = blockIdx.z;
    const float* in = x + (long long)bz * CDIM * LDIM;
    __half* xth = g_xTh + (long long)bz * LDIM * CDIM;

    int l = blockIdx.x * 32 + threadIdx.x;
    int c = blockIdx.y * 32 + threadIdx.y;
#pragma unroll
    for (int j = 0; j < 32; j += 8)
        tile[threadIdx.y + j][threadIdx.x] = in[(long long)(c + j) * LDIM + l];
    __syncthreads();
    int c2 = blockIdx.y * 32 + threadIdx.x;
    int l2 = blockIdx.x * 32 + threadIdx.y;
#pragma unroll
    for (int j = 0; j < 32; j += 8)
        xth[(long long)(l2 + j) * CDIM + c2] = __float2half_rn(tile[threadIdx.x][threadIdx.y + j]);
}

// partial column sums of E2: partial[b][my][l] = sum_{m in chunk my} E2[b][m][l]
// grid (4, 16, 8), block 256; each thread: 2 adjacent l via half2, 128 m rows
__global__ void __launch_bounds__(256) colsum_kernel()
{
    const int bz = blockIdx.z;
    const int l2 = blockIdx.x * 512 + threadIdx.x * 2;
    const __half* p = g_E2 + (long long)bz * LDIM * LDIM +
                      (long long)(blockIdx.y * 128) * LDIM + l2;
    float s0 = 0.f, s1 = 0.f;
#pragma unroll 4
    for (int r = 0; r < 128; ++r) {
        __half2 v = *(const __half2*)(p + (long long)r * LDIM);
        float2 f = __half22float2(v);
        s0 += f.x; s1 += f.y;
    }
    float* q = g_part + ((long long)(bz * 16 + blockIdx.y)) * LDIM + l2;
    q[0] = s0; q[1] = s1;
}

// reduce 16 partials -> reciprocal per column. grid(8), block 1024
__global__ void __launch_bounds__(1024) reduce_rcp_kernel()
{
    const int bz = blockIdx.x;
#pragma unroll
    for (int h = 0; h < 2; ++h) {
        int col = threadIdx.x + h * 1024;
        float s = 0.f;
#pragma unroll
        for (int sp = 0; sp < 16; ++sp)
            s += g_part[((long long)(bz * 16 + sp)) * LDIM + col];
        g_rcp[bz * LDIM + col] = 1.0f / s;
    }
}

extern "C" void kernel_launch(void* const* d_in, const int* in_sizes, int n_in,
                              void* d_out, int out_size)
{
    const float* x  = (const float*)d_in[0];
    const float* Wk = (const float*)d_in[1];
    const float* bk = (const float*)d_in[2];
    const float* Wq = (const float*)d_in[3];
    const float* bq = (const float*)d_in[4];
    const float* Wp = (const float*)d_in[5];
    const float* bp = (const float*)d_in[6];
    float* out = (float*)d_out;

    const int SMEM = 4 * TILE_HALVES * 2;   // 73728 bytes
    cudaFuncSetAttribute(hgemm_kernel<1, __half>, cudaFuncAttributeMaxDynamicSharedMemorySize, SMEM);
    cudaFuncSetAttribute(hgemm_kernel<2, __half>, cudaFuncAttributeMaxDynamicSharedMemorySize, SMEM);
    cudaFuncSetAttribute(hgemm_kernel<3, float>,  cudaFuncAttributeMaxDynamicSharedMemorySize, SMEM);
    cudaFuncSetAttribute(hgemm_kernel<4, __half>, cudaFuncAttributeMaxDynamicSharedMemorySize, SMEM);

    __half *p_w2h, *p_wph, *p_xTh, *p_kqT, *p_E2, *p_y;
    float *p_b2, *p_rcp;
    cudaGetSymbolAddress((void**)&p_w2h, g_w2h);
    cudaGetSymbolAddress((void**)&p_b2,  g_b2);
    cudaGetSymbolAddress((void**)&p_wph, g_wph);
    cudaGetSymbolAddress((void**)&p_xTh, g_xTh);
    cudaGetSymbolAddress((void**)&p_kqT, g_kqT);
    cudaGetSymbolAddress((void**)&p_E2,  g_E2);
    cudaGetSymbolAddress((void**)&p_rcp, g_rcp);
    cudaGetSymbolAddress((void**)&p_y,   g_y);

    // 0) operand prep
    concat_w_kernel<<<(256 * 1024 + 255) / 256, 256>>>(Wk, bk, Wq, bq);
    round_wp_kernel<<<(CDIM * CDIM + 255) / 256, 256>>>(Wp);
    xprep_kernel<<<dim3(LDIM / 32, CDIM / 32, BATCH), dim3(32, 8)>>>(x);

    // 1) kqT[l,a] = xTh[l,:]·W2[a,:] + b2[a]
    hgemm_kernel<1, __half><<<dim3(256 / BN, LDIM / BM, BATCH), 256, SMEM>>>(
        p_xTh, p_w2h, p_b2, p_kqT,
        CDIM, CDIM, CDIM, 256,
        (long long)LDIM * CDIM, 0LL, (long long)LDIM * 256);

    // 2) E2[m,l] = exp((qT[m,:]·kT[l,:])/1024)   K=128, half out
    hgemm_kernel<2, __half><<<dim3(LDIM / BN, LDIM / BM, BATCH), 256, SMEM>>>(
        p_kqT + 128, p_kqT, nullptr, p_E2,
        128, 256, 256, LDIM,
        (long long)LDIM * 256, (long long)LDIM * 256, (long long)LDIM * LDIM);

    // 3) rcp[l] = 1 / sum_m E2[m,l]
    colsum_kernel<<<dim3(4, 16, BATCH), 256>>>();
    reduce_rcp_kernel<<<BATCH, 1024>>>();

    // 4) y'[d,l] = (Wp[d,:]·xTh[l,:]) * rcp[l]   K=1024, half out
    hgemm_kernel<4, __half><<<dim3(LDIM / BN, CDIM / BM, BATCH), 256, SMEM>>>(
        p_wph, p_xTh, p_rcp, p_y,
        CDIM, CDIM, CDIM, LDIM,
        0LL, (long long)LDIM * CDIM, (long long)CDIM * LDIM);

    // 5) out[d,m] = y'[d,:]·E2[m,:] + bp[d]   K=2048, f32 out
    hgemm_kernel<3, float><<<dim3(LDIM / BN, CDIM / BM, BATCH), 256, SMEM>>>(
        p_y, p_E2, bp, out,
        LDIM, LDIM, LDIM, LDIM,
        (long long)CDIM * LDIM, (long long)LDIM * LDIM, (long long)CDIM * LDIM);
}